// round 12
// baseline (speedup 1.0000x reference)
#include <cuda_runtime.h>
#include <cuda_bf16.h>
#include <cstdint>

// SparseBoundaryContent: x [16, 512, 64] f32.
// boundary(i,j) = (x[i]+x[j])/2 on masked cells, content(i,j) = max(x[i..j])
// on masked cells, 0 elsewhere.
// Output layout (flat f32): [boundary B*D*N*N][content B*D*N*N][mask B*N*N].
//
// R11: 8 rows/CTA, HALF-TILE double buffering. Buffer pair 0 always holds
// half 0 (i<32), pair 1 half 1 (i>=32); each pair is zero-filled ONCE and
// only its ~550 masked cells are rewritten per row. Bulk stores stay 1-2
// groups in flight; wait_group 1 frees a buffer a full row after its store
// was committed, so waits never block. 34.5KB smem -> 6 CTAs/SM.

#define NB 16
#define ND 512
#define NN 64
#define NCELLS 4096          // 64*64 cells per (b,d) row
#define HCELLS 2048          // cells per half-tile
#define NMASKED 1104         // masked cells per tile (incl. diagonal)
#define SPLIT 676            // meta entries with i < 32 (half 0)
#define RPC 8                // rows per CTA

constexpr bool cell_mask_ct(int i, int j) {
    int d = j - i;
    if (d < 0)  return false;
    if (d <= 15) return true;                              // stride-1 offsets 0..15
    if (d <= 31) return (d & 1) && !(i & 1);               // stride-2: odd 17..31, i even
    return (d >= 35) && ((d & 3) == 3) && !(i & 3);        // stride-4: 35,39,..,63, i%4==0
}

struct MaskTab { float m[NCELLS]; };
constexpr MaskTab gen_mask() {
    MaskTab t{};
    for (int i = 0; i < NN; i++)
        for (int j = 0; j < NN; j++)
            t.m[i * NN + j] = cell_mask_ct(i, j) ? 1.0f : 0.0f;
    return t;
}
__device__ constexpr MaskTab g_mask = gen_mask();

struct Meta { unsigned int m[NMASKED]; };
constexpr Meta gen_meta() {
    Meta t{};
    int cnt = 0;
    for (int i = 0; i < NN; i++) {                         // i-major: half 0 first
        for (int j = 0; j < NN; j++) {
            if (!cell_mask_ct(i, j)) continue;
            int len = j - i + 1;
            int k = 0;
            while ((1 << (k + 1)) <= len) k++;             // floor(log2(len))
            int ri = j + 1 - (1 << k);
            unsigned offL = (unsigned)(k * NN + i);
            unsigned offR = (unsigned)(k * NN + ri);
            t.m[cnt++] = (unsigned)(i * NN + j) | (offL << 12) | (offR << 21);
        }
    }
    return t;
}
__device__ constexpr Meta g_meta = gen_meta();

constexpr int count_half0() {
    int c = 0;
    for (int i = 0; i < 32; i++)
        for (int j = 0; j < NN; j++)
            if (cell_mask_ct(i, j)) c++;
    return c;
}
static_assert(count_half0() == SPLIT, "half-0 meta split mismatch");

__device__ __forceinline__ uint32_t smem_u32(const void* p) {
    uint32_t a;
    asm("{ .reg .u64 t; cvta.to.shared.u64 t, %1; cvt.u32.u64 %0, t; }"
        : "=r"(a) : "l"(p));
    return a;
}

__global__ void __launch_bounds__(256)
sbc_kernel(const float* __restrict__ x,
           float* __restrict__ boundary,
           float* __restrict__ content,
           float* __restrict__ mask_out)
{
    __shared__ float Mf[7 * NN];                       // sparse max table
    __shared__ alignas(128) float buf[2][2][HCELLS];   // [half][b|c][cell]  32KB

    const int bd0 = blockIdx.x * RPC;
    const int tid = threadIdx.x;
    const int wid = tid >> 5;
    const int lid = tid & 31;

    // Zero-fill all buffers ONCE; unmasked cells stay zero for all rows.
    const float4 z = make_float4(0.f, 0.f, 0.f, 0.f);
    #pragma unroll
    for (int p = 0; p < 8; p++)
        reinterpret_cast<float4*>(&buf[0][0][0])[p * 256 + tid] = z;

    // Preload this thread's meta descriptors (half0: 3, half1: 2).
    unsigned m0[3], m1[2];
    #pragma unroll
    for (int p = 0; p < 3; p++) {
        int idx = p * 256 + tid;
        m0[p] = (idx < SPLIT) ? g_meta.m[idx] : 0xFFFFFFFFu;
    }
    #pragma unroll
    for (int p = 0; p < 2; p++) {
        int idx = SPLIT + p * 256 + tid;
        m1[p] = (idx < NMASKED) ? g_meta.m[idx] : 0xFFFFFFFFu;
    }

    // CTAs holding a d==0 row emit the broadcast mask slice for their batch.
    if ((bd0 & (ND - 1)) == 0) {
        float* mp = mask_out + (size_t)(bd0 >> 9) * NCELLS;
        #pragma unroll
        for (int p = 0; p < 4; p++) {
            const int c0 = (p * 256 + tid) * 4;
            *reinterpret_cast<float4*>(mp + c0) =
                *reinterpret_cast<const float4*>(&g_mask.m[c0]);
        }
    }
    __syncthreads();   // zero-fill complete before first Mf build / scatter

    for (int r = 0; r < RPC; r++) {
        const int bd = bd0 + r;
        float* gb = boundary + (size_t)bd * NCELLS;
        float* gc = content  + (size_t)bd * NCELLS;

        // Warp 0 rebuilds Mf (last readers finished at prev iteration's final
        // barrier). Thread 224 concurrently frees buffer pair 0 (its store
        // was committed a full row ago -> wait is a no-op in steady state).
        if (wid == 0) {
            const float* xr = x + (size_t)bd * NN;
            Mf[lid]      = xr[lid];
            Mf[lid + 32] = xr[lid + 32];
            __syncwarp();
            #pragma unroll
            for (int k = 1; k < 7; k++) {
                const int h  = 1 << (k - 1);
                const int e1 = lid + 32;
                int o0 = lid + h; if (o0 > 63) o0 = 63;
                int o1 = e1  + h; if (o1 > 63) o1 = 63;
                const float a = fmaxf(Mf[(k - 1) * NN + lid], Mf[(k - 1) * NN + o0]);
                const float b = fmaxf(Mf[(k - 1) * NN + e1],  Mf[(k - 1) * NN + o1]);
                Mf[k * NN + lid] = a;
                Mf[k * NN + e1]  = b;
                __syncwarp();
            }
        } else if (tid == 224) {
            asm volatile("cp.async.bulk.wait_group 1;" ::: "memory");
        }
        __syncthreads();   // Mf ready AND buffer pair 0 free

        // Scatter half 0 (676 cells, i<32) into buffer pair 0.
        #pragma unroll
        for (int p = 0; p < 3; p++) {
            const unsigned m = m0[p];
            if (m != 0xFFFFFFFFu) {
                const int cell = m & 4095u;                // 0..2047
                const int gi   = cell >> 6;
                const int gj   = cell & 63;
                buf[0][0][cell] = (Mf[gi] + Mf[gj]) * 0.5f;
                buf[0][1][cell] = fmaxf(Mf[(m >> 12) & 511u], Mf[(m >> 21) & 511u]);
            }
        }
        asm volatile("fence.proxy.async.shared::cta;" ::: "memory");
        __syncthreads();   // half-0 scatter visible to async proxy

        if (tid == 224) {
            asm volatile("cp.async.bulk.global.shared::cta.bulk_group [%0], [%1], %2;"
                         :: "l"(gb), "r"(smem_u32(&buf[0][0][0])), "n"(HCELLS * 4) : "memory");
            asm volatile("cp.async.bulk.global.shared::cta.bulk_group [%0], [%1], %2;"
                         :: "l"(gc), "r"(smem_u32(&buf[0][1][0])), "n"(HCELLS * 4) : "memory");
            asm volatile("cp.async.bulk.commit_group;" ::: "memory");
            // Free buffer pair 1 (committed last row; only the group above may
            // remain pending).
            asm volatile("cp.async.bulk.wait_group 1;" ::: "memory");
        }
        __syncthreads();   // buffer pair 1 free for scatter

        // Scatter half 1 (428 cells, i>=32) into buffer pair 1.
        #pragma unroll
        for (int p = 0; p < 2; p++) {
            const unsigned m = m1[p];
            if (m != 0xFFFFFFFFu) {
                const int cell  = m & 4095u;               // 2048..4095
                const int local = cell - HCELLS;
                const int gi    = cell >> 6;
                const int gj    = cell & 63;
                buf[1][0][local] = (Mf[gi] + Mf[gj]) * 0.5f;
                buf[1][1][local] = fmaxf(Mf[(m >> 12) & 511u], Mf[(m >> 21) & 511u]);
            }
        }
        asm volatile("fence.proxy.async.shared::cta;" ::: "memory");
        __syncthreads();   // half-1 scatter visible; also last Mf read done

        if (tid == 224) {
            asm volatile("cp.async.bulk.global.shared::cta.bulk_group [%0], [%1], %2;"
                         :: "l"(gb + HCELLS), "r"(smem_u32(&buf[1][0][0])), "n"(HCELLS * 4) : "memory");
            asm volatile("cp.async.bulk.global.shared::cta.bulk_group [%0], [%1], %2;"
                         :: "l"(gc + HCELLS), "r"(smem_u32(&buf[1][1][0])), "n"(HCELLS * 4) : "memory");
            asm volatile("cp.async.bulk.commit_group;" ::: "memory");
        }
    }

    // Drain all stores before CTA teardown (smem reuse safety).
    if (tid == 224)
        asm volatile("cp.async.bulk.wait_group 0;" ::: "memory");
}

extern "C" void kernel_launch(void* const* d_in, const int* in_sizes, int n_in,
                              void* d_out, int out_size) {
    const float* x = (const float*)d_in[0];
    float* out = (float*)d_out;

    const size_t map_elems = (size_t)NB * ND * NN * NN;   // 33,554,432
    float* boundary = out;
    float* content  = out + map_elems;
    float* mask_out = out + 2 * map_elems;

    sbc_kernel<<<(NB * ND) / RPC, 256>>>(x, boundary, content, mask_out);
}

// round 13
// speedup vs baseline: 1.1829x; 1.1829x over previous
#include <cuda_runtime.h>
#include <cuda_bf16.h>
#include <cstdint>

// SparseBoundaryContent: x [16, 512, 64] f32.
// boundary(i,j) = (x[i]+x[j])/2 on masked cells, content(i,j) = max(x[i..j])
// on masked cells, 0 elsewhere.
// Output layout (flat f32): [boundary B*D*N*N][content B*D*N*N][mask B*N*N].
//
// R12: R5 champion structure (1 row/CTA, grid 8192, smem build + bulk store)
// with the CTA critical path compressed: 512 threads (4 CTAs/SM = 100% warp
// occupancy), warp-0 sparse-table build overlapped with zero-fill (2 block
// barriers total), early x load, dual-thread bulk-store issue.

#define NB 16
#define ND 512
#define NN 64
#define NCELLS 4096          // 64*64 cells per (b,d) row
#define NMASKED 1104         // masked cells per tile (incl. diagonal)
#define NT 512               // threads per CTA

constexpr bool cell_mask_ct(int i, int j) {
    int d = j - i;
    if (d < 0)  return false;
    if (d <= 15) return true;                              // stride-1 offsets 0..15
    if (d <= 31) return (d & 1) && !(i & 1);               // stride-2: odd 17..31, i even
    return (d >= 35) && ((d & 3) == 3) && !(i & 3);        // stride-4: 35,39,..,63, i%4==0
}

struct MaskTab { float m[NCELLS]; };
constexpr MaskTab gen_mask() {
    MaskTab t{};
    for (int i = 0; i < NN; i++)
        for (int j = 0; j < NN; j++)
            t.m[i * NN + j] = cell_mask_ct(i, j) ? 1.0f : 0.0f;
    return t;
}
__device__ constexpr MaskTab g_mask = gen_mask();

struct Meta { unsigned int m[NMASKED]; };
constexpr Meta gen_meta() {
    Meta t{};
    int cnt = 0;
    for (int i = 0; i < NN; i++) {
        for (int j = 0; j < NN; j++) {
            if (!cell_mask_ct(i, j)) continue;
            int len = j - i + 1;
            int k = 0;
            while ((1 << (k + 1)) <= len) k++;             // floor(log2(len))
            int ri = j + 1 - (1 << k);
            unsigned offL = (unsigned)(k * NN + i);
            unsigned offR = (unsigned)(k * NN + ri);
            t.m[cnt++] = (unsigned)(i * NN + j) | (offL << 12) | (offR << 21);
        }
    }
    return t;
}
__device__ constexpr Meta g_meta = gen_meta();

__device__ __forceinline__ uint32_t smem_u32(const void* p) {
    uint32_t a;
    asm("{ .reg .u64 t; cvta.to.shared.u64 t, %1; cvt.u32.u64 %0, t; }"
        : "=r"(a) : "l"(p));
    return a;
}

__global__ void __launch_bounds__(NT)
sbc_kernel(const float* __restrict__ x,
           float* __restrict__ boundary,
           float* __restrict__ content,
           float* __restrict__ mask_out)
{
    __shared__ float Mf[7 * NN];                 // sparse max table
    __shared__ alignas(128) float bt[NCELLS];    // boundary tile (16 KB)
    __shared__ alignas(128) float ct[NCELLS];    // content tile  (16 KB)

    const int bd  = blockIdx.x;                  // bd = b*ND + d
    const int tid = threadIdx.x;
    const int wid = tid >> 5;
    const int lid = tid & 31;

    // Warp 0: load x row EARLY and build the sparse-max table (syncwarp only).
    // All warps (incl. warp 0): zero-fill both tiles (4 float4 each).
    if (wid == 0) {
        const float* xr = x + (size_t)bd * NN;
        const float x0 = xr[lid];
        const float x1 = xr[lid + 32];
        // zero-fill share first so the LDG latency is covered by these stores
        const float4 z = make_float4(0.f, 0.f, 0.f, 0.f);
        #pragma unroll
        for (int p = 0; p < 2; p++) {
            reinterpret_cast<float4*>(bt)[p * NT + tid] = z;
            reinterpret_cast<float4*>(ct)[p * NT + tid] = z;
        }
        Mf[lid]      = x0;
        Mf[lid + 32] = x1;
        __syncwarp();
        #pragma unroll
        for (int k = 1; k < 7; k++) {
            const int h  = 1 << (k - 1);
            const int e1 = lid + 32;
            int o0 = lid + h; if (o0 > 63) o0 = 63;
            int o1 = e1  + h; if (o1 > 63) o1 = 63;
            const float a = fmaxf(Mf[(k - 1) * NN + lid], Mf[(k - 1) * NN + o0]);
            const float b = fmaxf(Mf[(k - 1) * NN + e1],  Mf[(k - 1) * NN + o1]);
            Mf[k * NN + lid] = a;
            Mf[k * NN + e1]  = b;
            __syncwarp();
        }
    } else {
        const float4 z = make_float4(0.f, 0.f, 0.f, 0.f);
        #pragma unroll
        for (int p = 0; p < 2; p++) {
            reinterpret_cast<float4*>(bt)[p * NT + tid] = z;
            reinterpret_cast<float4*>(ct)[p * NT + tid] = z;
        }
    }
    __syncthreads();   // Mf ready, tiles zeroed

    // Scatter boundary + content at the 1104 masked cells (<=3 per thread).
    #pragma unroll
    for (int p = 0; p < 3; p++) {
        const int idx = p * NT + tid;
        if (idx < NMASKED) {
            const unsigned m    = g_meta.m[idx];
            const int      cell = m & 4095u;
            const int      i    = cell >> 6;
            const int      j    = cell & 63;
            bt[cell] = (Mf[i] + Mf[j]) * 0.5f;
            ct[cell] = fmaxf(Mf[(m >> 12) & 511u], Mf[(m >> 21) & 511u]);
        }
    }

    asm volatile("fence.proxy.async.shared::cta;" ::: "memory");
    __syncthreads();   // scatter + zero-fill visible to async proxy

    // Dual-thread bulk-store issue: two independent bulk groups.
    if (tid == 0) {
        float* gb = boundary + (size_t)bd * NCELLS;
        asm volatile("cp.async.bulk.global.shared::cta.bulk_group [%0], [%1], %2;"
                     :: "l"(gb), "r"(smem_u32(bt)), "n"(NCELLS * 4) : "memory");
        asm volatile("cp.async.bulk.commit_group;" ::: "memory");
    } else if (tid == 256) {
        float* gc = content + (size_t)bd * NCELLS;
        asm volatile("cp.async.bulk.global.shared::cta.bulk_group [%0], [%1], %2;"
                     :: "l"(gc), "r"(smem_u32(ct)), "n"(NCELLS * 4) : "memory");
        asm volatile("cp.async.bulk.commit_group;" ::: "memory");
    }

    // 16 CTAs (d == 0) emit the broadcast mask slice for their batch b.
    if ((bd & (ND - 1)) == 0) {
        float* mp = mask_out + (size_t)(bd >> 9) * NCELLS;
        #pragma unroll
        for (int p = 0; p < 2; p++) {
            const int c0 = (p * NT + tid) * 4;
            *reinterpret_cast<float4*>(mp + c0) =
                *reinterpret_cast<const float4*>(&g_mask.m[c0]);
        }
    }

    // Each issuing thread drains its own group before CTA teardown.
    if (tid == 0 || tid == 256)
        asm volatile("cp.async.bulk.wait_group 0;" ::: "memory");
}

extern "C" void kernel_launch(void* const* d_in, const int* in_sizes, int n_in,
                              void* d_out, int out_size) {
    const float* x = (const float*)d_in[0];
    float* out = (float*)d_out;

    const size_t map_elems = (size_t)NB * ND * NN * NN;   // 33,554,432
    float* boundary = out;
    float* content  = out + map_elems;
    float* mask_out = out + 2 * map_elems;

    sbc_kernel<<<NB * ND, NT>>>(x, boundary, content, mask_out);
}

// round 14
// speedup vs baseline: 1.2475x; 1.0546x over previous
#include <cuda_runtime.h>
#include <cuda_bf16.h>
#include <cstdint>

// SparseBoundaryContent: x [16, 512, 64] f32.
// boundary(i,j) = (x[i]+x[j])/2 on masked cells, content(i,j) = max(x[i..j])
// on masked cells, 0 elsewhere.
// Output layout (flat f32): [boundary B*D*N*N][content B*D*N*N][mask B*N*N].
//
// R13: champion R5 structure (1 row/CTA, grid 8192, 256 threads, smem build,
// cp.async.bulk stores) with the critical path compressed: warp-0 sparse-max
// build (syncwarp-only) overlapped with the other warps' zero-fill, early x
// load, dual-thread bulk-store issue. 2 block barriers per CTA.
// NOTE: kernel is at the chip-wide LTS store cap (~6300 B/cyc); output bytes
// are irreducible, so this is within a few % of the hardware floor.

#define NB 16
#define ND 512
#define NN 64
#define NCELLS 4096          // 64*64 cells per (b,d) row
#define NMASKED 1104         // masked cells per tile (incl. diagonal)

constexpr bool cell_mask_ct(int i, int j) {
    int d = j - i;
    if (d < 0)  return false;
    if (d <= 15) return true;                              // stride-1 offsets 0..15
    if (d <= 31) return (d & 1) && !(i & 1);               // stride-2: odd 17..31, i even
    return (d >= 35) && ((d & 3) == 3) && !(i & 3);        // stride-4: 35,39,..,63, i%4==0
}

struct MaskTab { float m[NCELLS]; };
constexpr MaskTab gen_mask() {
    MaskTab t{};
    for (int i = 0; i < NN; i++)
        for (int j = 0; j < NN; j++)
            t.m[i * NN + j] = cell_mask_ct(i, j) ? 1.0f : 0.0f;
    return t;
}
__device__ constexpr MaskTab g_mask = gen_mask();

struct Meta { unsigned int m[NMASKED]; };
constexpr Meta gen_meta() {
    Meta t{};
    int cnt = 0;
    for (int i = 0; i < NN; i++) {
        for (int j = 0; j < NN; j++) {
            if (!cell_mask_ct(i, j)) continue;
            int len = j - i + 1;
            int k = 0;
            while ((1 << (k + 1)) <= len) k++;             // floor(log2(len))
            int ri = j + 1 - (1 << k);
            unsigned offL = (unsigned)(k * NN + i);
            unsigned offR = (unsigned)(k * NN + ri);
            t.m[cnt++] = (unsigned)(i * NN + j) | (offL << 12) | (offR << 21);
        }
    }
    return t;
}
__device__ constexpr Meta g_meta = gen_meta();

__device__ __forceinline__ uint32_t smem_u32(const void* p) {
    uint32_t a;
    asm("{ .reg .u64 t; cvta.to.shared.u64 t, %1; cvt.u32.u64 %0, t; }"
        : "=r"(a) : "l"(p));
    return a;
}

__global__ void __launch_bounds__(256)
sbc_kernel(const float* __restrict__ x,
           float* __restrict__ boundary,
           float* __restrict__ content,
           float* __restrict__ mask_out)
{
    __shared__ float Mf[7 * NN];                 // sparse max table
    __shared__ alignas(128) float bt[NCELLS];    // boundary tile (16 KB)
    __shared__ alignas(128) float ct[NCELLS];    // content tile  (16 KB)

    const int bd  = blockIdx.x;                  // bd = b*ND + d
    const int tid = threadIdx.x;
    const int wid = tid >> 5;
    const int lid = tid & 31;

    // Warp 0: early x load + sparse-max table build (syncwarp only), with its
    // zero-fill share issued between the LDG and its first use (latency hide).
    // Warps 1..7: zero-fill the two 16 KB tiles.
    if (wid == 0) {
        const float* xr = x + (size_t)bd * NN;
        const float x0 = xr[lid];
        const float x1 = xr[lid + 32];
        const float4 z = make_float4(0.f, 0.f, 0.f, 0.f);
        #pragma unroll
        for (int p = 0; p < 4; p++) {
            reinterpret_cast<float4*>(bt)[p * 256 + tid] = z;
            reinterpret_cast<float4*>(ct)[p * 256 + tid] = z;
        }
        Mf[lid]      = x0;
        Mf[lid + 32] = x1;
        __syncwarp();
        #pragma unroll
        for (int k = 1; k < 7; k++) {
            const int h  = 1 << (k - 1);
            const int e1 = lid + 32;
            int o0 = lid + h; if (o0 > 63) o0 = 63;
            int o1 = e1  + h; if (o1 > 63) o1 = 63;
            const float a = fmaxf(Mf[(k - 1) * NN + lid], Mf[(k - 1) * NN + o0]);
            const float b = fmaxf(Mf[(k - 1) * NN + e1],  Mf[(k - 1) * NN + o1]);
            Mf[k * NN + lid] = a;
            Mf[k * NN + e1]  = b;
            __syncwarp();
        }
    } else {
        const float4 z = make_float4(0.f, 0.f, 0.f, 0.f);
        #pragma unroll
        for (int p = 0; p < 4; p++) {
            reinterpret_cast<float4*>(bt)[p * 256 + tid] = z;
            reinterpret_cast<float4*>(ct)[p * 256 + tid] = z;
        }
    }
    __syncthreads();   // Mf ready, tiles zeroed

    // Scatter boundary + content at the 1104 masked cells (<=5 per thread).
    #pragma unroll
    for (int p = 0; p < 5; p++) {
        const int idx = p * 256 + tid;
        if (idx < NMASKED) {
            const unsigned m    = g_meta.m[idx];
            const int      cell = m & 4095u;
            const int      i    = cell >> 6;
            const int      j    = cell & 63;
            bt[cell] = (Mf[i] + Mf[j]) * 0.5f;
            ct[cell] = fmaxf(Mf[(m >> 12) & 511u], Mf[(m >> 21) & 511u]);
        }
    }

    asm volatile("fence.proxy.async.shared::cta;" ::: "memory");
    __syncthreads();   // scatter + zero-fill visible to async proxy

    // Dual-thread bulk-store issue: two independent bulk groups.
    if (tid == 0) {
        float* gb = boundary + (size_t)bd * NCELLS;
        asm volatile("cp.async.bulk.global.shared::cta.bulk_group [%0], [%1], %2;"
                     :: "l"(gb), "r"(smem_u32(bt)), "n"(NCELLS * 4) : "memory");
        asm volatile("cp.async.bulk.commit_group;" ::: "memory");
    } else if (tid == 128) {
        float* gc = content + (size_t)bd * NCELLS;
        asm volatile("cp.async.bulk.global.shared::cta.bulk_group [%0], [%1], %2;"
                     :: "l"(gc), "r"(smem_u32(ct)), "n"(NCELLS * 4) : "memory");
        asm volatile("cp.async.bulk.commit_group;" ::: "memory");
    }

    // 16 CTAs (d == 0) emit the broadcast mask slice for their batch b.
    if ((bd & (ND - 1)) == 0) {
        float* mp = mask_out + (size_t)(bd >> 9) * NCELLS;
        #pragma unroll
        for (int p = 0; p < 4; p++) {
            const int c0 = (p * 256 + tid) * 4;
            *reinterpret_cast<float4*>(mp + c0) =
                *reinterpret_cast<const float4*>(&g_mask.m[c0]);
        }
    }

    // Each issuing thread drains its own group before CTA teardown.
    if (tid == 0 || tid == 128)
        asm volatile("cp.async.bulk.wait_group 0;" ::: "memory");
}

extern "C" void kernel_launch(void* const* d_in, const int* in_sizes, int n_in,
                              void* d_out, int out_size) {
    const float* x = (const float*)d_in[0];
    float* out = (float*)d_out;

    const size_t map_elems = (size_t)NB * ND * NN * NN;   // 33,554,432
    float* boundary = out;
    float* content  = out + map_elems;
    float* mask_out = out + 2 * map_elems;

    sbc_kernel<<<NB * ND, 256>>>(x, boundary, content, mask_out);
}